// round 13
// baseline (speedup 1.0000x reference)
#include <cuda_runtime.h>
#include <cuda_fp16.h>
#include <cuda_bf16.h>

// ---- physical constants (double-precision derived, matching reference) ----
#define KEHALF      7.199822675975274f
#define CUTON_F     2.5f
#define CUTOFF_F    7.5f
#define LRCUT_F     10.0f
#define CUTON16_F   2328306.4365386963f
#define CUT_RCONST  0.009999999997526174f
#define CUT_CONST   0.19999999999608f
#define INV_RANGE   0.2f
#define INV_LR2     0.01f
#define TWO_OVER_LR 0.2f

#define MAX_N 102400
#define MAX_M 2048
#define NSLOT 64

// fp16 charge table (200KB): L1D-resident; serves BOTH i- and j-side gathers
__device__ __half d_qh[MAX_N];
// slot-strided scratch (128K addresses): block flushes land here
__device__ float  d_scratch[MAX_M * NSLOT];
// monotone failure flag: statically 0, only ever OR'd (no reset -> no race).
__device__ int    d_bad = 0;

__global__ __launch_bounds__(256)
void prep_kernel(const float* __restrict__ q,
                 const int* __restrict__ idx_m,
                 int N, unsigned magic32) {
    int stride = gridDim.x * blockDim.x;
    int tid = blockIdx.x * blockDim.x + threadIdx.x;

    // vectorized convert + exhaustive verification of the EXACT umulhi formula
    const float4* q4 = (const float4*)q;
    const int4*   m4 = (const int4*)idx_m;
    uint2*        h4 = (uint2*)d_qh;          // 4 halves = uint2
    bool ok = (magic32 != 0u);
    int N4 = N >> 2;
    for (int v = tid; v < N4; v += stride) {
        float4 qv = q4[v];
        int4   mv = m4[v];
        __half2 lo = __floats2half2_rn(qv.x, qv.y);
        __half2 hi = __floats2half2_rn(qv.z, qv.w);
        h4[v] = make_uint2(*(unsigned*)&lo, *(unsigned*)&hi);
        unsigned i0 = 4u * (unsigned)v;
        ok &= (__umulhi(i0 + 0u, magic32) == (unsigned)mv.x);
        ok &= (__umulhi(i0 + 1u, magic32) == (unsigned)mv.y);
        ok &= (__umulhi(i0 + 2u, magic32) == (unsigned)mv.z);
        ok &= (__umulhi(i0 + 3u, magic32) == (unsigned)mv.w);
    }
    // scalar tail (N % 4)
    for (int i = (N4 << 2) + tid; i < N; i += stride) {
        d_qh[i] = __float2half_rn(q[i]);
        ok &= (__umulhi((unsigned)i, magic32) == (unsigned)idx_m[i]);
    }
    if (!ok) atomicOr(&d_bad, 1);

    // zero the flush scratch (float4 stores)
    float4* s4 = (float4*)d_scratch;
    const float4 z = make_float4(0.f, 0.f, 0.f, 0.f);
    for (int v = tid; v < (MAX_M * NSLOT) / 4; v += stride) s4[v] = z;
}

__device__ __forceinline__ float edge_energy(float x, float y, float z,
                                             float qi, float qj) {
    float s  = fmaf(x, x, fmaf(y, y, z * z));   // d^2
    float rd = rsqrtf(s);                       // 1/d
    float d  = s * rd;                          // d
    float fac = KEHALF * qi * qj;

    // smooth switch; single-RCP form:
    //   1/t - 1/(1-t) = (1-2t) / (t - t^2)
    //   f = 1 / (1 + exp(g))
    float f;
    if (d >= CUTOFF_F) {
        f = 0.0f;
    } else if (d <= CUTON_F) {
        f = 1.0f;
    } else {
        float t  = (CUTOFF_F - d) * INV_RANGE;       // in (0,1)
        float tm = fmaf(-t, t, t);                   // t - t^2 > 0
        float g  = (1.0f - 2.0f * t) * __frcp_rn(tm);
        f = __fdividef(1.0f, 1.0f + __expf(g));
    }

    float d4  = s * s;
    float d8  = d4 * d4;
    float d16 = d8 * d8;
    float p   = exp2f(-0.0625f * __log2f(d16 + CUTON16_F));

    float omf    = 1.0f - f;
    float damped = fmaf(omf * CUT_RCONST, d, p - CUT_CONST);
    float coul   = (d < LRCUT_F) ? (rd + fmaf(d, INV_LR2, -TWO_OVER_LR)) : 0.0f;
    return fac * fmaf(f, damped, omf * coul);
}

// 8KB static smem only -> L1D keeps ~220KB -> fp16 q table is L1-resident.
// Per-edge atomics: ALL smem ATOMS (R7-proven optimal; in-loop global REDs
// measured ~5us/25% share slower in R9/R11; 2048-address REDs fatal in R8).
__global__ __launch_bounds__(512, 3)
void energy_kernel(const float4* __restrict__ r4,
                   const float*  __restrict__ q,
                   const int4*   __restrict__ ii4,
                   const int4*   __restrict__ jj4,
                   const float*  __restrict__ r_scalar,
                   const int*    __restrict__ idx_i,
                   const int*    __restrict__ idx_j,
                   const int*    __restrict__ idx_m,
                   int P, int M, unsigned magic32) {
    __shared__ float ymol[MAX_M];
    for (int b = threadIdx.x; b < MAX_M; b += blockDim.x) ymol[b] = 0.0f;
    __syncthreads();

    const bool fast = (d_bad == 0);
    int gwarp = blockIdx.x * (blockDim.x >> 5) + (threadIdx.x >> 5);
    int slot  = gwarp & (NSLOT - 1);

    int gid    = blockIdx.x * blockDim.x + threadIdx.x;
    int stride = gridDim.x * blockDim.x;
    int P4 = P >> 2;

    if (fast) {
        for (int g = gid; g < P4; g += stride) {
            float4 a = __ldcs(&r4[3 * g + 0]);
            float4 b = __ldcs(&r4[3 * g + 1]);
            float4 c = __ldcs(&r4[3 * g + 2]);
            int4 ii = __ldcs(&ii4[g]);
            int4 jj = __ldcs(&jj4[g]);

            // 8 independent 2B gathers from the L1-resident fp16 table
            float qi0 = __half2float(d_qh[ii.x]);
            float qi1 = __half2float(d_qh[ii.y]);
            float qi2 = __half2float(d_qh[ii.z]);
            float qi3 = __half2float(d_qh[ii.w]);
            float qj0 = __half2float(d_qh[jj.x]);
            float qj1 = __half2float(d_qh[jj.y]);
            float qj2 = __half2float(d_qh[jj.z]);
            float qj3 = __half2float(d_qh[jj.w]);
            // molecule bins: one umulhi each (verified exhaustively in prep)
            int m0 = (int)__umulhi((unsigned)ii.x, magic32);
            int m1 = (int)__umulhi((unsigned)ii.y, magic32);
            int m2 = (int)__umulhi((unsigned)ii.z, magic32);
            int m3 = (int)__umulhi((unsigned)ii.w, magic32);

            float e0 = edge_energy(a.x, a.y, a.z, qi0, qj0);
            float e1 = edge_energy(a.w, b.x, b.y, qi1, qj1);
            float e2 = edge_energy(b.z, b.w, c.x, qi2, qj2);
            float e3 = edge_energy(c.y, c.z, c.w, qi3, qj3);

            atomicAdd(&ymol[m0], e0);
            atomicAdd(&ymol[m1], e1);
            atomicAdd(&ymol[m2], e2);
            atomicAdd(&ymol[m3], e3);
        }
        for (int e = (P4 << 2) + gid; e < P; e += stride) {
            float x = r_scalar[3 * e + 0];
            float y = r_scalar[3 * e + 1];
            float z = r_scalar[3 * e + 2];
            int i = idx_i[e];
            float qi = __half2float(d_qh[i]);
            float qj = __half2float(d_qh[idx_j[e]]);
            int m = (int)__umulhi((unsigned)i, magic32);
            atomicAdd(&ymol[m], edge_energy(x, y, z, qi, qj));
        }
    } else {
        // correctness fallback: fp32 q + gathered idx_m
        for (int e = gid; e < P; e += stride) {
            float x = r_scalar[3 * e + 0];
            float y = r_scalar[3 * e + 1];
            float z = r_scalar[3 * e + 2];
            int i = idx_i[e];
            float ev = edge_energy(x, y, z, __ldg(&q[i]), __ldg(&q[idx_j[e]]));
            atomicAdd(&ymol[idx_m[i]], ev);
        }
    }

    // flush block bins into slot-strided scratch (fire-and-forget RED)
    __syncthreads();
    for (int b = threadIdx.x; b < M; b += blockDim.x) {
        float v = ymol[b];
        if (v != 0.0f) atomicAdd(&d_scratch[b * NSLOT + slot], v);
    }
}

// warp per bin: coalesced float2/lane over the 64-slot row, shfl-reduce,
// WRITE out (out is poisoned; every bin is written). Read-only on scratch.
__global__ __launch_bounds__(256)
void combine_kernel(float* __restrict__ out, int M) {
    int warp = (blockIdx.x * blockDim.x + threadIdx.x) >> 5;
    int lane = threadIdx.x & 31;
    if (warp < M) {
        float2 v = ((const float2*)&d_scratch[warp * NSLOT])[lane];
        float s = v.x + v.y;
        #pragma unroll
        for (int off = 16; off > 0; off >>= 1)
            s += __shfl_down_sync(0xffffffffu, s, off);
        if (lane == 0) out[warp] = s;
    }
}

// host-level fallback for shapes outside the design envelope
__global__ __launch_bounds__(256)
void energy_fallback(const float* __restrict__ r_scalar,
                     const float* __restrict__ q,
                     const int*   __restrict__ idx_i,
                     const int*   __restrict__ idx_j,
                     const int*   __restrict__ idx_m,
                     int P, float* __restrict__ out) {
    int gid    = blockIdx.x * blockDim.x + threadIdx.x;
    int stride = gridDim.x * blockDim.x;
    for (int e = gid; e < P; e += stride) {
        float x = r_scalar[3 * e + 0];
        float y = r_scalar[3 * e + 1];
        float z = r_scalar[3 * e + 2];
        int i = idx_i[e];
        float ev = edge_energy(x, y, z, q[i], q[idx_j[e]]);
        atomicAdd(&out[idx_m[i]], ev);
    }
}

__global__ void zero_out(float* __restrict__ out, int M) {
    int i = blockIdx.x * blockDim.x + threadIdx.x;
    if (i < M) out[i] = 0.0f;
}

extern "C" void kernel_launch(void* const* d_in, const int* in_sizes, int n_in,
                              void* d_out, int out_size) {
    // metadata order: atomic_numbers, q, r_ij, idx_i, idx_j, idx_m, maxm
    const float* q     = (const float*)d_in[1];
    const float* r_ij  = (const float*)d_in[2];
    const int*   idx_i = (const int*)d_in[3];
    const int*   idx_j = (const int*)d_in[4];
    const int*   idx_m = (const int*)d_in[5];
    int N = in_sizes[1];
    int P = in_sizes[3];
    int M = out_size;
    float* out = (float*)d_out;

    if (N > MAX_N || M > MAX_M || N < 2 || M < 1) {
        zero_out<<<(M + 255) / 256, 256>>>(out, M);
        energy_fallback<<<1184, 256>>>(r_ij, q, idx_i, idx_j, idx_m, P, out);
        return;
    }

    // 32-bit magic divider: m = umulhi(i, magic32) == i/apm, verified
    // exhaustively in prep (if verification fails -> gathered fallback path).
    unsigned magic32 = 0;
    if (N % M == 0 && (N / M) > 1) {
        unsigned long long apm = (unsigned long long)(N / M);
        unsigned long long mg  = (0x100000000ULL + apm - 1) / apm;  // ceil(2^32/apm)
        if (mg <= 0xFFFFFFFFULL) magic32 = (unsigned)mg;
    }

    prep_kernel<<<592, 256>>>(q, idx_m, N, magic32);

    int sm_count = 148;
    cudaDeviceGetAttribute(&sm_count, cudaDevAttrMultiProcessorCount, 0);
    int blocks = sm_count * 3;   // 3 CTAs/SM @ 512 threads = 48 warps/SM

    energy_kernel<<<blocks, 512>>>(
        (const float4*)r_ij, q, (const int4*)idx_i, (const int4*)idx_j,
        r_ij, idx_i, idx_j, idx_m, P, M, magic32);

    combine_kernel<<<(M * 32 + 255) / 256, 256>>>(out, M);
}

// round 14
// speedup vs baseline: 1.0876x; 1.0876x over previous
#include <cuda_runtime.h>
#include <cuda_fp16.h>
#include <cuda_bf16.h>

// ---- physical constants (double-precision derived, matching reference) ----
#define KEHALF      7.199822675975274f
#define CUTON_F     2.5f
#define CUTOFF_F    7.5f
#define LRCUT_F     10.0f
#define CUTON16_F   2328306.4365386963f
#define CUT_RCONST  0.009999999997526174f
#define CUT_CONST   0.19999999999608f
#define INV_RANGE   0.2f
#define INV_LR2     0.01f
#define TWO_OVER_LR 0.2f

#define MAX_N 102400
#define MAX_M 2048
#define NSLOT 64

// fp16 charge table (200KB): L1D-resident; serves BOTH i- and j-side gathers
__device__ __half d_qh[MAX_N];
// slot-strided scratch (128K addresses): block flushes land here
__device__ float  d_scratch[MAX_M * NSLOT];
// monotone failure flag: statically 0, only ever OR'd (no reset -> no race).
__device__ int    d_bad = 0;

__global__ __launch_bounds__(256)
void prep_kernel(const float* __restrict__ q,
                 const int* __restrict__ idx_m,
                 int N, unsigned magic32) {
    int stride = gridDim.x * blockDim.x;
    int tid = blockIdx.x * blockDim.x + threadIdx.x;

    // vectorized convert + exhaustive verification of the EXACT umulhi formula
    const float4* q4 = (const float4*)q;
    const int4*   m4 = (const int4*)idx_m;
    uint2*        h4 = (uint2*)d_qh;          // 4 halves = uint2
    bool ok = (magic32 != 0u);
    int N4 = N >> 2;
    for (int v = tid; v < N4; v += stride) {
        float4 qv = q4[v];
        int4   mv = m4[v];
        __half2 lo = __floats2half2_rn(qv.x, qv.y);
        __half2 hi = __floats2half2_rn(qv.z, qv.w);
        h4[v] = make_uint2(*(unsigned*)&lo, *(unsigned*)&hi);
        unsigned i0 = 4u * (unsigned)v;
        ok &= (__umulhi(i0 + 0u, magic32) == (unsigned)mv.x);
        ok &= (__umulhi(i0 + 1u, magic32) == (unsigned)mv.y);
        ok &= (__umulhi(i0 + 2u, magic32) == (unsigned)mv.z);
        ok &= (__umulhi(i0 + 3u, magic32) == (unsigned)mv.w);
    }
    // scalar tail (N % 4)
    for (int i = (N4 << 2) + tid; i < N; i += stride) {
        d_qh[i] = __float2half_rn(q[i]);
        ok &= (__umulhi((unsigned)i, magic32) == (unsigned)idx_m[i]);
    }
    if (!ok) atomicOr(&d_bad, 1);

    // zero the flush scratch (float4 stores)
    float4* s4 = (float4*)d_scratch;
    const float4 z = make_float4(0.f, 0.f, 0.f, 0.f);
    for (int v = tid; v < (MAX_M * NSLOT) / 4; v += stride) s4[v] = z;
}

__device__ __forceinline__ float edge_energy(float x, float y, float z,
                                             float qi, float qj) {
    float s  = fmaf(x, x, fmaf(y, y, z * z));   // d^2
    float rd = rsqrtf(s);                       // 1/d
    float d  = s * rd;                          // d
    float fac = KEHALF * qi * qj;

    // smooth switch; single-RCP algebra, FAST division (MUFU.RCP path):
    //   1/t - 1/(1-t) = (1-2t)/(t - t^2);  f = 1/(1 + exp(g))
    float f;
    if (d >= CUTOFF_F) {
        f = 0.0f;
    } else if (d <= CUTON_F) {
        f = 1.0f;
    } else {
        float t  = (CUTOFF_F - d) * INV_RANGE;       // in (0,1)
        float tm = fmaf(-t, t, t);                   // t - t^2 > 0
        float g  = (1.0f - 2.0f * t) * __fdividef(1.0f, tm);
        f = __fdividef(1.0f, 1.0f + __expf(g));
    }

    float d4  = s * s;
    float d8  = d4 * d4;
    float d16 = d8 * d8;
    float p   = exp2f(-0.0625f * __log2f(d16 + CUTON16_F));

    float omf    = 1.0f - f;
    float damped = fmaf(omf * CUT_RCONST, d, p - CUT_CONST);
    float coul   = (d < LRCUT_F) ? (rd + fmaf(d, INV_LR2, -TWO_OVER_LR)) : 0.0f;
    return fac * fmaf(f, damped, omf * coul);
}

// 8KB static smem only -> L1D keeps ~220KB -> fp16 q table is L1-resident.
// Per-edge atomics: ALL smem ATOMS (R7-proven optimal; in-loop global REDs
// measured ~5us/25% share slower in R9/R11; 2048-address REDs fatal in R8).
__global__ __launch_bounds__(512, 3)
void energy_kernel(const float4* __restrict__ r4,
                   const float*  __restrict__ q,
                   const int4*   __restrict__ ii4,
                   const int4*   __restrict__ jj4,
                   const float*  __restrict__ r_scalar,
                   const int*    __restrict__ idx_i,
                   const int*    __restrict__ idx_j,
                   const int*    __restrict__ idx_m,
                   int P, int M, unsigned magic32) {
    __shared__ float ymol[MAX_M];
    for (int b = threadIdx.x; b < MAX_M; b += blockDim.x) ymol[b] = 0.0f;
    __syncthreads();

    const bool fast = (d_bad == 0);
    int gwarp = blockIdx.x * (blockDim.x >> 5) + (threadIdx.x >> 5);
    int slot  = gwarp & (NSLOT - 1);

    int gid    = blockIdx.x * blockDim.x + threadIdx.x;
    int stride = gridDim.x * blockDim.x;
    int P4 = P >> 2;

    if (fast) {
        for (int g = gid; g < P4; g += stride) {
            float4 a = __ldcs(&r4[3 * g + 0]);
            float4 b = __ldcs(&r4[3 * g + 1]);
            float4 c = __ldcs(&r4[3 * g + 2]);
            int4 ii = __ldcs(&ii4[g]);
            int4 jj = __ldcs(&jj4[g]);

            // 8 independent 2B gathers from the L1-resident fp16 table
            float qi0 = __half2float(d_qh[ii.x]);
            float qi1 = __half2float(d_qh[ii.y]);
            float qi2 = __half2float(d_qh[ii.z]);
            float qi3 = __half2float(d_qh[ii.w]);
            float qj0 = __half2float(d_qh[jj.x]);
            float qj1 = __half2float(d_qh[jj.y]);
            float qj2 = __half2float(d_qh[jj.z]);
            float qj3 = __half2float(d_qh[jj.w]);
            // molecule bins: one umulhi each (verified exhaustively in prep)
            int m0 = (int)__umulhi((unsigned)ii.x, magic32);
            int m1 = (int)__umulhi((unsigned)ii.y, magic32);
            int m2 = (int)__umulhi((unsigned)ii.z, magic32);
            int m3 = (int)__umulhi((unsigned)ii.w, magic32);

            float e0 = edge_energy(a.x, a.y, a.z, qi0, qj0);
            float e1 = edge_energy(a.w, b.x, b.y, qi1, qj1);
            float e2 = edge_energy(b.z, b.w, c.x, qi2, qj2);
            float e3 = edge_energy(c.y, c.z, c.w, qi3, qj3);

            atomicAdd(&ymol[m0], e0);
            atomicAdd(&ymol[m1], e1);
            atomicAdd(&ymol[m2], e2);
            atomicAdd(&ymol[m3], e3);
        }
        for (int e = (P4 << 2) + gid; e < P; e += stride) {
            float x = r_scalar[3 * e + 0];
            float y = r_scalar[3 * e + 1];
            float z = r_scalar[3 * e + 2];
            int i = idx_i[e];
            float qi = __half2float(d_qh[i]);
            float qj = __half2float(d_qh[idx_j[e]]);
            int m = (int)__umulhi((unsigned)i, magic32);
            atomicAdd(&ymol[m], edge_energy(x, y, z, qi, qj));
        }
    } else {
        // correctness fallback: fp32 q + gathered idx_m
        for (int e = gid; e < P; e += stride) {
            float x = r_scalar[3 * e + 0];
            float y = r_scalar[3 * e + 1];
            float z = r_scalar[3 * e + 2];
            int i = idx_i[e];
            float ev = edge_energy(x, y, z, __ldg(&q[i]), __ldg(&q[idx_j[e]]));
            atomicAdd(&ymol[idx_m[i]], ev);
        }
    }

    // flush block bins into slot-strided scratch (fire-and-forget RED)
    __syncthreads();
    for (int b = threadIdx.x; b < M; b += blockDim.x) {
        float v = ymol[b];
        if (v != 0.0f) atomicAdd(&d_scratch[b * NSLOT + slot], v);
    }
}

// warp per bin: coalesced float2/lane over the 64-slot row, shfl-reduce,
// WRITE out (out is poisoned; every bin is written). Read-only on scratch.
__global__ __launch_bounds__(256)
void combine_kernel(float* __restrict__ out, int M) {
    int warp = (blockIdx.x * blockDim.x + threadIdx.x) >> 5;
    int lane = threadIdx.x & 31;
    if (warp < M) {
        float2 v = ((const float2*)&d_scratch[warp * NSLOT])[lane];
        float s = v.x + v.y;
        #pragma unroll
        for (int off = 16; off > 0; off >>= 1)
            s += __shfl_down_sync(0xffffffffu, s, off);
        if (lane == 0) out[warp] = s;
    }
}

// host-level fallback for shapes outside the design envelope
__global__ __launch_bounds__(256)
void energy_fallback(const float* __restrict__ r_scalar,
                     const float* __restrict__ q,
                     const int*   __restrict__ idx_i,
                     const int*   __restrict__ idx_j,
                     const int*   __restrict__ idx_m,
                     int P, float* __restrict__ out) {
    int gid    = blockIdx.x * blockDim.x + threadIdx.x;
    int stride = gridDim.x * blockDim.x;
    for (int e = gid; e < P; e += stride) {
        float x = r_scalar[3 * e + 0];
        float y = r_scalar[3 * e + 1];
        float z = r_scalar[3 * e + 2];
        int i = idx_i[e];
        float ev = edge_energy(x, y, z, q[i], q[idx_j[e]]);
        atomicAdd(&out[idx_m[i]], ev);
    }
}

__global__ void zero_out(float* __restrict__ out, int M) {
    int i = blockIdx.x * blockDim.x + threadIdx.x;
    if (i < M) out[i] = 0.0f;
}

extern "C" void kernel_launch(void* const* d_in, const int* in_sizes, int n_in,
                              void* d_out, int out_size) {
    // metadata order: atomic_numbers, q, r_ij, idx_i, idx_j, idx_m, maxm
    const float* q     = (const float*)d_in[1];
    const float* r_ij  = (const float*)d_in[2];
    const int*   idx_i = (const int*)d_in[3];
    const int*   idx_j = (const int*)d_in[4];
    const int*   idx_m = (const int*)d_in[5];
    int N = in_sizes[1];
    int P = in_sizes[3];
    int M = out_size;
    float* out = (float*)d_out;

    if (N > MAX_N || M > MAX_M || N < 2 || M < 1) {
        zero_out<<<(M + 255) / 256, 256>>>(out, M);
        energy_fallback<<<1184, 256>>>(r_ij, q, idx_i, idx_j, idx_m, P, out);
        return;
    }

    // 32-bit magic divider: m = umulhi(i, magic32) == i/apm, verified
    // exhaustively in prep (if verification fails -> gathered fallback path).
    unsigned magic32 = 0;
    if (N % M == 0 && (N / M) > 1) {
        unsigned long long apm = (unsigned long long)(N / M);
        unsigned long long mg  = (0x100000000ULL + apm - 1) / apm;  // ceil(2^32/apm)
        if (mg <= 0xFFFFFFFFULL) magic32 = (unsigned)mg;
    }

    prep_kernel<<<592, 256>>>(q, idx_m, N, magic32);

    int sm_count = 148;
    cudaDeviceGetAttribute(&sm_count, cudaDevAttrMultiProcessorCount, 0);
    int blocks = sm_count * 3;   // 3 CTAs/SM @ 512 threads = 48 warps/SM

    energy_kernel<<<blocks, 512>>>(
        (const float4*)r_ij, q, (const int4*)idx_i, (const int4*)idx_j,
        r_ij, idx_i, idx_j, idx_m, P, M, magic32);

    combine_kernel<<<(M * 32 + 255) / 256, 256>>>(out, M);
}